// round 13
// baseline (speedup 1.0000x reference)
#include <cuda_runtime.h>
#include <cuda_bf16.h>

#define N_NODES 100000
#define E_EDGES 1600000
#define FDIM    128
#define OUTDIM  384
#define SLOT    64          // fixed bucket capacity; P(deg>=64) ~ 1e-22

// Scratch __device__ globals — referenced ONLY from device code (GB300 trap:
// host-side use of a __device__ symbol silently hits the coherent host shadow).
// NOTE: g_degi starts zero-initialized (module load) and is RE-ZEROED by
// k_agg2 after its final read, so no zeroing launch is needed per replay.
__device__ __align__(16) __nv_bfloat16 g_fb [(size_t)N_NODES * FDIM]; // feat, bf16
__device__ __align__(16) __nv_bfloat16 g_h1b[(size_t)N_NODES * FDIM]; // h1,   bf16
__device__ __align__(16) int g_slot[(size_t)N_NODES * SLOT];          // src ids per dst
__device__ int g_degi[N_NODES];
__device__ int g_is64;

struct alignas(8) bf4 { __nv_bfloat162 a, b; };

// ---------------------------------------------------------------------------
// Launch 1 (tiny): dtype detect only.
__global__ void k_detect(const void* __restrict__ ei) {
    __shared__ int ok;
    if (threadIdx.x == 0) ok = 1;
    __syncthreads();
    const int stride = E_EDGES / 64;
    long long v = ((const long long*)ei)[(size_t)threadIdx.x * stride];
    if (v < 0 || v >= N_NODES) atomicAnd(&ok, 0);
    __syncthreads();
    if (threadIdx.x == 0) g_is64 = ok;
}

// ---------------------------------------------------------------------------
// Launch 2 (mega): feat copy (streaming stores) + bf16 mirror, and direct
// bucket-CSR build (g_degi assumed zero on entry; agg2 restores it).
#define PREP_BL ((N_NODES * (FDIM / 4) + 255) / 256)   // 12500
#define NORM_BL ((E_EDGES + 255) / 256)                 // 6250
__global__ void k_mega(const float* __restrict__ feat,
                       const void*  __restrict__ ei,
                       float*       __restrict__ out) {
    if (blockIdx.x < PREP_BL) {
        const int total4 = N_NODES * (FDIM / 4);
        int i = blockIdx.x * blockDim.x + threadIdx.x;
        if (i >= total4) return;
        int node = i >> 5;
        int c4   = i & 31;
        float4 f = reinterpret_cast<const float4*>(feat)[i];
        // out block0 is never re-read: stream it past L2.
        __stcs(reinterpret_cast<float4*>(out) + (size_t)node * (OUTDIM / 4) + c4, f);
        bf4 b;
        b.a = __floats2bfloat162_rn(f.x, f.y);
        b.b = __floats2bfloat162_rn(f.z, f.w);
        reinterpret_cast<bf4*>(g_fb)[i] = b;   // default cache: re-read by agg1
    } else {
        int e = (blockIdx.x - PREP_BL) * blockDim.x + threadIdx.x;
        if (e >= E_EDGES) return;
        long long s, d;
        if (g_is64) {
            s = ((const long long*)ei)[e];
            d = ((const long long*)ei)[(size_t)E_EDGES + e];
        } else {
            s = ((const int*)ei)[e];
            d = ((const int*)ei)[(size_t)E_EDGES + e];
        }
        if (s < 0) s = 0;  if (s >= N_NODES) s = N_NODES - 1;
        if (d < 0) d = 0;  if (d >= N_NODES) d = N_NODES - 1;
        int p = atomicAdd(&g_degi[(int)d], 1);
        if (p < SLOT) g_slot[(size_t)d * SLOT + p] = (int)s;
    }
}

// ---------------------------------------------------------------------------
// Exact bf16x2 -> 2x fp32 accumulate via bit expansion (no extra rounding).
__device__ __forceinline__ void acc_expand(float& alo, float& ahi, __nv_bfloat162 p) {
    unsigned int bits = *reinterpret_cast<unsigned int*>(&p);
    alo += __uint_as_float(bits << 16);
    ahi += __uint_as_float(bits & 0xFFFF0000u);
}

__device__ __forceinline__ void acc_bf4v(float4& acc, bf4 v) {
    acc_expand(acc.x, acc.y, v.a);
    acc_expand(acc.z, acc.w, v.b);
}

// Gather+mean: warp per node, lane owns 4 bf16 channels (LDG.64), MLP=8.
// RESET_DEG: zero g_degi[w] after the final read (replay-to-replay reset).
template <bool WRITE_H1B, bool RESET_DEG>
__device__ __forceinline__ void agg_body(const __nv_bfloat16* __restrict__ src,
                                         float* __restrict__ out, int out_blk) {
    int w    = (blockIdx.x * blockDim.x + threadIdx.x) >> 5;
    int lane = threadIdx.x & 31;
    if (w >= N_NODES) return;
    int deg = g_degi[w];
    if (RESET_DEG && lane == 0) g_degi[w] = 0;
    if (deg > SLOT) deg = SLOT;
    const int4* sl4 = reinterpret_cast<const int4*>(g_slot + (size_t)w * SLOT);
    const char* base = reinterpret_cast<const char*>(src) + lane * 8;

    float4 acc = make_float4(0.f, 0.f, 0.f, 0.f);
    int i = 0;
    for (; i + 8 <= deg; i += 8) {
        int4 sa = sl4[(i >> 2) + 0];
        int4 sb = sl4[(i >> 2) + 1];
        bf4 v0 = *reinterpret_cast<const bf4*>(base + ((size_t)sa.x << 8));
        bf4 v1 = *reinterpret_cast<const bf4*>(base + ((size_t)sa.y << 8));
        bf4 v2 = *reinterpret_cast<const bf4*>(base + ((size_t)sa.z << 8));
        bf4 v3 = *reinterpret_cast<const bf4*>(base + ((size_t)sa.w << 8));
        bf4 v4 = *reinterpret_cast<const bf4*>(base + ((size_t)sb.x << 8));
        bf4 v5 = *reinterpret_cast<const bf4*>(base + ((size_t)sb.y << 8));
        bf4 v6 = *reinterpret_cast<const bf4*>(base + ((size_t)sb.z << 8));
        bf4 v7 = *reinterpret_cast<const bf4*>(base + ((size_t)sb.w << 8));
        acc_bf4v(acc, v0); acc_bf4v(acc, v1); acc_bf4v(acc, v2); acc_bf4v(acc, v3);
        acc_bf4v(acc, v4); acc_bf4v(acc, v5); acc_bf4v(acc, v6); acc_bf4v(acc, v7);
    }
    if (i + 4 <= deg) {
        int4 s = sl4[i >> 2];
        bf4 v0 = *reinterpret_cast<const bf4*>(base + ((size_t)s.x << 8));
        bf4 v1 = *reinterpret_cast<const bf4*>(base + ((size_t)s.y << 8));
        bf4 v2 = *reinterpret_cast<const bf4*>(base + ((size_t)s.z << 8));
        bf4 v3 = *reinterpret_cast<const bf4*>(base + ((size_t)s.w << 8));
        acc_bf4v(acc, v0); acc_bf4v(acc, v1); acc_bf4v(acc, v2); acc_bf4v(acc, v3);
        i += 4;
    }
    if (i < deg) {
        int4 s = sl4[i >> 2];
        int r = deg - i;   // 1..3
        bf4 v0 = *reinterpret_cast<const bf4*>(base + ((size_t)s.x << 8));
        acc_bf4v(acc, v0);
        if (r > 1) {
            bf4 v1 = *reinterpret_cast<const bf4*>(base + ((size_t)s.y << 8));
            acc_bf4v(acc, v1);
        }
        if (r > 2) {
            bf4 v2 = *reinterpret_cast<const bf4*>(base + ((size_t)s.z << 8));
            acc_bf4v(acc, v2);
        }
    }

    float inv = deg > 0 ? __frcp_rn((float)deg) : 0.f;
    acc.x *= inv; acc.y *= inv; acc.z *= inv; acc.w *= inv;
    // out blocks are never re-read: stream past L2 to protect gather tables.
    __stcs(reinterpret_cast<float4*>(out + (size_t)w * OUTDIM + out_blk * FDIM + lane * 4), acc);
    if (WRITE_H1B) {
        bf4 b;
        b.a = __floats2bfloat162_rn(acc.x, acc.y);
        b.b = __floats2bfloat162_rn(acc.z, acc.w);
        *reinterpret_cast<bf4*>(g_h1b + (size_t)w * FDIM + lane * 4) = b;  // cached: agg2 reads
    }
}

// Launch 3: layer-1 mean-agg (feat bf16 -> out block1 + h1 bf16 mirror).
__global__ void __launch_bounds__(256) k_agg1(float* __restrict__ out) {
    agg_body<true, false>(g_fb, out, 1);
}

// Launch 4: layer-2 mean-agg (h1 bf16 -> out block2) + g_degi reset.
__global__ void __launch_bounds__(256) k_agg2(float* __restrict__ out) {
    agg_body<false, true>(g_h1b, out, 2);
}

// ---------------------------------------------------------------------------
extern "C" void kernel_launch(void* const* d_in, const int* in_sizes, int n_in,
                              void* d_out, int out_size) {
    const float* feat = (const float*)d_in[0];
    const void*  ei   = d_in[1];
    float*       out  = (float*)d_out;

    const int T = 256;
    const int warp_bl = (N_NODES * 32 + T - 1) / T;

    k_detect<<<1, 64>>>(ei);                           // 1 (tiny)
    k_mega<<<PREP_BL + NORM_BL, T>>>(feat, ei, out);   // 2
    k_agg1<<<warp_bl, T>>>(out);                       // 3
    k_agg2<<<warp_bl, T>>>(out);                       // 4
}

// round 15
// speedup vs baseline: 2.0266x; 2.0266x over previous
#include <cuda_runtime.h>
#include <cuda_bf16.h>

#define N_NODES 100000
#define E_EDGES 1600000
#define FDIM    128
#define OUTDIM  384
#define SLOT    64          // fixed bucket capacity; P(deg>=64) ~ 1e-22

// Scratch __device__ globals — referenced ONLY from device code (GB300 trap:
// host-side use of a __device__ symbol silently hits the coherent host shadow).
__device__ __align__(16) __nv_bfloat16 g_fb [(size_t)N_NODES * FDIM]; // feat, bf16
__device__ __align__(16) __nv_bfloat16 g_h1b[(size_t)N_NODES * FDIM]; // h1,   bf16
__device__ __align__(16) int g_slot[(size_t)N_NODES * SLOT];          // src ids per dst
__device__ int g_degi[N_NODES];
__device__ int g_is64;

struct alignas(8) bf4 { __nv_bfloat162 a, b; };

// ---------------------------------------------------------------------------
// Launch 1: zero degree histogram + dtype detect (block 0).  (R11 structure)
__global__ void k_detect_zero(const void* __restrict__ ei) {
    int i = blockIdx.x * blockDim.x + threadIdx.x;
    if (i < N_NODES) g_degi[i] = 0;

    if (blockIdx.x == 0) {
        __shared__ int ok;
        if (threadIdx.x == 0) ok = 1;
        __syncthreads();
        if (threadIdx.x < 64) {
            const int stride = E_EDGES / 64;
            long long v = ((const long long*)ei)[(size_t)threadIdx.x * stride];
            if (v < 0 || v >= N_NODES) atomicAnd(&ok, 0);
        }
        __syncthreads();
        if (threadIdx.x == 0) g_is64 = ok;
    }
}

// ---------------------------------------------------------------------------
// Launch 2 (mega): feat copy + bf16 mirror, and direct bucket-CSR build.
// out block0 is never re-read -> streaming store (evict-first) to avoid
// evicting the gather tables (g_fb/g_h1b/g_slot) from L2.
#define PREP_BL ((N_NODES * (FDIM / 4) + 255) / 256)   // 12500
#define NORM_BL ((E_EDGES + 255) / 256)                 // 6250
__global__ void k_mega(const float* __restrict__ feat,
                       const void*  __restrict__ ei,
                       float*       __restrict__ out) {
    if (blockIdx.x < PREP_BL) {
        const int total4 = N_NODES * (FDIM / 4);
        int i = blockIdx.x * blockDim.x + threadIdx.x;
        if (i >= total4) return;
        int node = i >> 5;
        int c4   = i & 31;
        float4 f = reinterpret_cast<const float4*>(feat)[i];
        __stcs(reinterpret_cast<float4*>(out) + (size_t)node * (OUTDIM / 4) + c4, f);
        bf4 b;
        b.a = __floats2bfloat162_rn(f.x, f.y);
        b.b = __floats2bfloat162_rn(f.z, f.w);
        reinterpret_cast<bf4*>(g_fb)[i] = b;   // default cache: re-read by agg1
    } else {
        int e = (blockIdx.x - PREP_BL) * blockDim.x + threadIdx.x;
        if (e >= E_EDGES) return;
        long long s, d;
        if (g_is64) {
            s = ((const long long*)ei)[e];
            d = ((const long long*)ei)[(size_t)E_EDGES + e];
        } else {
            s = ((const int*)ei)[e];
            d = ((const int*)ei)[(size_t)E_EDGES + e];
        }
        if (s < 0) s = 0;  if (s >= N_NODES) s = N_NODES - 1;
        if (d < 0) d = 0;  if (d >= N_NODES) d = N_NODES - 1;
        int p = atomicAdd(&g_degi[(int)d], 1);
        if (p < SLOT) g_slot[(size_t)d * SLOT + p] = (int)s;
    }
}

// ---------------------------------------------------------------------------
// Exact bf16x2 -> 2x fp32 accumulate via bit expansion (no extra rounding).
__device__ __forceinline__ void acc_expand(float& alo, float& ahi, __nv_bfloat162 p) {
    unsigned int bits = *reinterpret_cast<unsigned int*>(&p);
    alo += __uint_as_float(bits << 16);
    ahi += __uint_as_float(bits & 0xFFFF0000u);
}

__device__ __forceinline__ void acc_bf4v(float4& acc, bf4 v) {
    acc_expand(acc.x, acc.y, v.a);
    acc_expand(acc.z, acc.w, v.b);
}

// Gather+mean: warp per node, lane owns 4 bf16 channels (LDG.64), MLP=8.
// EXACT R11 body — no same-address degi store (R13 lesson), only the out
// store switched to __stcs.
template <bool WRITE_H1B>
__device__ __forceinline__ void agg_body(const __nv_bfloat16* __restrict__ src,
                                         float* __restrict__ out, int out_blk) {
    int w    = (blockIdx.x * blockDim.x + threadIdx.x) >> 5;
    int lane = threadIdx.x & 31;
    if (w >= N_NODES) return;
    int deg = g_degi[w];
    if (deg > SLOT) deg = SLOT;
    const int4* sl4 = reinterpret_cast<const int4*>(g_slot + (size_t)w * SLOT);
    const char* base = reinterpret_cast<const char*>(src) + lane * 8;

    float4 acc = make_float4(0.f, 0.f, 0.f, 0.f);
    int i = 0;
    for (; i + 8 <= deg; i += 8) {
        int4 sa = sl4[(i >> 2) + 0];
        int4 sb = sl4[(i >> 2) + 1];
        bf4 v0 = *reinterpret_cast<const bf4*>(base + ((size_t)sa.x << 8));
        bf4 v1 = *reinterpret_cast<const bf4*>(base + ((size_t)sa.y << 8));
        bf4 v2 = *reinterpret_cast<const bf4*>(base + ((size_t)sa.z << 8));
        bf4 v3 = *reinterpret_cast<const bf4*>(base + ((size_t)sa.w << 8));
        bf4 v4 = *reinterpret_cast<const bf4*>(base + ((size_t)sb.x << 8));
        bf4 v5 = *reinterpret_cast<const bf4*>(base + ((size_t)sb.y << 8));
        bf4 v6 = *reinterpret_cast<const bf4*>(base + ((size_t)sb.z << 8));
        bf4 v7 = *reinterpret_cast<const bf4*>(base + ((size_t)sb.w << 8));
        acc_bf4v(acc, v0); acc_bf4v(acc, v1); acc_bf4v(acc, v2); acc_bf4v(acc, v3);
        acc_bf4v(acc, v4); acc_bf4v(acc, v5); acc_bf4v(acc, v6); acc_bf4v(acc, v7);
    }
    if (i + 4 <= deg) {
        int4 s = sl4[i >> 2];
        bf4 v0 = *reinterpret_cast<const bf4*>(base + ((size_t)s.x << 8));
        bf4 v1 = *reinterpret_cast<const bf4*>(base + ((size_t)s.y << 8));
        bf4 v2 = *reinterpret_cast<const bf4*>(base + ((size_t)s.z << 8));
        bf4 v3 = *reinterpret_cast<const bf4*>(base + ((size_t)s.w << 8));
        acc_bf4v(acc, v0); acc_bf4v(acc, v1); acc_bf4v(acc, v2); acc_bf4v(acc, v3);
        i += 4;
    }
    if (i < deg) {
        int4 s = sl4[i >> 2];
        int r = deg - i;   // 1..3
        bf4 v0 = *reinterpret_cast<const bf4*>(base + ((size_t)s.x << 8));
        acc_bf4v(acc, v0);
        if (r > 1) {
            bf4 v1 = *reinterpret_cast<const bf4*>(base + ((size_t)s.y << 8));
            acc_bf4v(acc, v1);
        }
        if (r > 2) {
            bf4 v2 = *reinterpret_cast<const bf4*>(base + ((size_t)s.z << 8));
            acc_bf4v(acc, v2);
        }
    }

    float inv = deg > 0 ? __frcp_rn((float)deg) : 0.f;
    acc.x *= inv; acc.y *= inv; acc.z *= inv; acc.w *= inv;
    __stcs(reinterpret_cast<float4*>(out + (size_t)w * OUTDIM + out_blk * FDIM + lane * 4), acc);
    if (WRITE_H1B) {
        bf4 b;
        b.a = __floats2bfloat162_rn(acc.x, acc.y);
        b.b = __floats2bfloat162_rn(acc.z, acc.w);
        *reinterpret_cast<bf4*>(g_h1b + (size_t)w * FDIM + lane * 4) = b;  // cached: agg2 reads
    }
}

// Launch 3: layer-1 mean-agg (feat bf16 -> out block1 + h1 bf16 mirror).
__global__ void __launch_bounds__(256) k_agg1(float* __restrict__ out) {
    agg_body<true>(g_fb, out, 1);
}

// Launch 4: layer-2 mean-agg (h1 bf16 -> out block2).
__global__ void __launch_bounds__(256) k_agg2(float* __restrict__ out) {
    agg_body<false>(g_h1b, out, 2);
}

// ---------------------------------------------------------------------------
extern "C" void kernel_launch(void* const* d_in, const int* in_sizes, int n_in,
                              void* d_out, int out_size) {
    const float* feat = (const float*)d_in[0];
    const void*  ei   = d_in[1];
    float*       out  = (float*)d_out;

    const int T = 256;
    const int warp_bl = (N_NODES * 32 + T - 1) / T;
    const int zero_bl = (N_NODES + 1023) / 1024;

    k_detect_zero<<<zero_bl, 1024>>>(ei);              // 1
    k_mega<<<PREP_BL + NORM_BL, T>>>(feat, ei, out);   // 2
    k_agg1<<<warp_bl, T>>>(out);                       // 3
    k_agg2<<<warp_bl, T>>>(out);                       // 4
}